// round 15
// baseline (speedup 1.0000x reference)
#include <cuda_runtime.h>
#include <cstdint>

// resRNN: x(256,1024,8), W1(521,512), b1(512), W2(512,1), b2(1)
// out = [output(256,1024,1) | implied_storage(256,1024,1)]
//
// R6 skeleton (proven replay-stable), 512 threads: 16 warps = 8 k-parts x
// 2 col-halves. Warp (kp,ch): k in [kp*68,kp*68+68), cols ch*32+lane (1 col
// per lane -> no W smem duplication; input loads are single-phase broadcasts).
// Exchange/barriers/tanhf byte-for-byte R6.

#define TPB 512

static __device__ float g_hx[2][256][512];       // double-buffered hidden state
static __device__ float g_part[2][16][8][16];    // per-(rg,cg,row) readout partials

// shared memory layout (float offsets); inpT stride = 20 (16 rows + 4 pad)
#define OFF_W    0              // 544*64   = 34816 floats
#define OFF_IT   34816          // 544*20   = 10880 floats (inpT[k][20])
#define OFF_RED  45696          // 8*16*68  =  8704 floats
#define OFF_B1   54400          // 64
#define OFF_W2   54464          // 64
#define OFF_S    54528          // 16
#define SMEM_FLOATS 54544
#define SMEM_BYTES (SMEM_FLOATS * 4)

__global__ void __cluster_dims__(8, 1, 1) __launch_bounds__(512, 1)
resRNN_kernel(const float* __restrict__ x, const float* __restrict__ W1,
              const float* __restrict__ b1, const float* __restrict__ W2,
              const float* __restrict__ b2, float* __restrict__ dout)
{
    extern __shared__ float sm[];
    float* Wsm  = sm + OFF_W;
    float* inpT = sm + OFF_IT;
    float* red  = sm + OFF_RED;
    float* b1s  = sm + OFF_B1;
    float* w2s  = sm + OFF_W2;
    float* s_sm = sm + OFF_S;

    const int tid  = threadIdx.x;
    const int warp = tid >> 5;
    const int lane = tid & 31;
    const int kp   = warp & 7;     // k-partition 0..7
    const int ch   = warp >> 3;    // col-half 0..1
    const int col  = ch * 32 + lane;   // this thread's hidden column (0..63)
    const int cg   = blockIdx.x;   // colgroup 0..7
    const int rg   = blockIdx.y;   // rowgroup 0..15
    const int row0 = rg * 16;

    // ---- init: load W1 slice [544 x 64] (zero-pad k>=521), zero inpT ----
    for (int i = tid; i < 544 * 16; i += TPB) {
        int k = i >> 4, f4 = i & 15;
        float4 v = make_float4(0.f, 0.f, 0.f, 0.f);
        if (k < 521) v = *(const float4*)&W1[k * 512 + cg * 64 + f4 * 4];
        *(float4*)&Wsm[k * 64 + f4 * 4] = v;
    }
    for (int i = tid; i < 544 * 20; i += TPB) inpT[i] = 0.f;
    if (tid < 64) { b1s[tid] = b1[cg * 64 + tid]; w2s[tid] = W2[cg * 64 + tid]; }
    const float b2v = b2[0];
    float* outp = dout;
    float* stop = dout + 256 * 1024;

    // pre-loop: stage x_0 into inpT, s_0 = x_0[0]; prefetch x_1
    const int xr = tid >> 3, xc = tid & 7;
    float xpre = 0.f, x0pre = 0.f;
    if (tid < 128) {
        float xv = x[(row0 + xr) * 8192 + xc];
        inpT[xc * 20 + xr] = xv;
        xpre = x[(row0 + xr) * 8192 + 8 + xc];         // x_1
    }
    if (tid < 16) {
        float s = x[(row0 + tid) * 8192];              // s_0 = x_0[0] (prev out = 0)
        s_sm[tid] = s;
        inpT[8 * 20 + tid] = s;
        if (cg == 0) stop[(row0 + tid) * 1024] = s;
        x0pre = x[(row0 + tid) * 8192 + 8];            // x_1[0] (for Phase A at t=1)
    }
    __syncthreads();

    for (int t = 0; t < 1024; ++t) {
        const int pw = t & 1;        // write parity
        const int pr = pw ^ 1;       // read parity = (t-1)&1

        // ---- Phase A: gather out_{t-1}; mass balance; transpose hx into inpT ----
        if (t > 0) {
            if (tid < 16) {
                float o = b2v;
                #pragma unroll
                for (int g = 0; g < 8; ++g) o += __ldcg(&g_part[pr][rg][g][tid]);
                // s_t = s_{t-1} + x_t[0] - out_{t-1}
                float s = s_sm[tid] + x0pre - o;
                s_sm[tid] = s;
                inpT[8 * 20 + tid] = s;
                if (cg == 0) {
                    outp[(row0 + tid) * 1024 + (t - 1)] = o;
                    stop[(row0 + tid) * 1024 + t] = s;
                }
            }
            // hx transpose: thread owns hidden column tid (512 threads = 512 cols)
            float v0[16];
            #pragma unroll
            for (int r = 0; r < 16; ++r) v0[r] = __ldcg(&g_hx[pr][row0 + r][tid]);
            float* d0 = &inpT[(9 + tid) * 20];
            #pragma unroll
            for (int q = 0; q < 8; ++q)
                *(float2*)(d0 + 2 * q) = make_float2(v0[2*q], v0[2*q+1]);
        }
        __syncthreads();

        // ---- Phase C: mainloop. warp (kp,ch): k in [kp*68,kp*68+68),
        //      16 rows, 1 col per lane (col = ch*32+lane). acc[p] = row-pair p.
        unsigned long long acc[8];
        #pragma unroll
        for (int i = 0; i < 8; ++i) acc[i] = 0ull;
        {
            const float* Ip = inpT + kp * 68 * 20;
            const float* Wp = Wsm + kp * 68 * 64 + col;
            #pragma unroll 4
            for (int kk = 0; kk < 68; ++kk) {
                unsigned long long pr_[8];
                #pragma unroll
                for (int j = 0; j < 4; ++j) {
                    ulonglong2 q = *(const ulonglong2*)(Ip + kk * 20 + 4 * j);
                    pr_[2 * j] = q.x; pr_[2 * j + 1] = q.y;
                }
                float wv = Wp[kk * 64];
                unsigned long long ww;
                asm("mov.b64 %0, {%1, %1};" : "=l"(ww) : "f"(wv));
                #pragma unroll
                for (int p = 0; p < 8; ++p)
                    asm("fma.rn.f32x2 %0, %1, %2, %0;" : "+l"(acc[p]) : "l"(pr_[p]), "l"(ww));
            }
        }

        // ---- Phase D: spill k-partials, reduce, tanh, emit hx + readout partial ----
        #pragma unroll
        for (int p = 0; p < 8; ++p) {
            float2 a = *(float2*)&acc[p];     // rows (2p, 2p+1), this col
            red[(kp * 16 + 2 * p)     * 68 + col] = a.x;
            red[(kp * 16 + 2 * p + 1) * 68 + col] = a.y;
        }
        __syncthreads();
        {
            // 512 threads: warp r handles row r (16 warps = 16 rows), lane -> 2 cols
            int r = warp, c2 = 2 * lane;
            float2 v = make_float2(0.f, 0.f);
            #pragma unroll
            for (int w = 0; w < 8; ++w) {
                float2 p = *(const float2*)&red[(w * 16 + r) * 68 + c2];
                v.x += p.x; v.y += p.y;
            }
            v.x = tanhf(v.x + b1s[c2]);
            v.y = tanhf(v.y + b1s[c2 + 1]);
            *(float2*)&g_hx[pw][row0 + r][cg * 64 + c2] = v;
            float p = v.x * w2s[c2] + v.y * w2s[c2 + 1];
            #pragma unroll
            for (int off = 16; off > 0; off >>= 1)
                p += __shfl_xor_sync(0xffffffffu, p, off);
            if (lane == 0) g_part[pw][rg][cg][r] = p;
        }

        // ---- Phase E: split cluster barrier; x staging hides in the gap ----
        asm volatile("barrier.cluster.arrive.aligned;" ::: "memory");
        if (t < 1023) {
            if (tid < 128) {
                inpT[xc * 20 + xr] = xpre;                           // stage x_{t+1}
                if (t < 1022) xpre = x[(row0 + xr) * 8192 + (t + 2) * 8 + xc];
            }
            // x0 for next step's Phase A = x_{t+1}[0]
            if (tid < 16) x0pre = x[(row0 + tid) * 8192 + (t + 1) * 8];
        }
        asm volatile("barrier.cluster.wait.aligned;" ::: "memory");
    }

    // epilogue: final output value out_{L-1}
    if (cg == 0 && tid < 16) {
        float o = b2v;
        #pragma unroll
        for (int g = 0; g < 8; ++g) o += __ldcg(&g_part[1][rg][g][tid]);
        outp[(row0 + tid) * 1024 + 1023] = o;
    }
}

extern "C" void kernel_launch(void* const* d_in, const int* in_sizes, int n_in,
                              void* d_out, int out_size) {
    const float* x  = (const float*)d_in[0];
    const float* W1 = (const float*)d_in[1];
    const float* b1 = (const float*)d_in[2];
    const float* W2 = (const float*)d_in[3];
    const float* b2 = (const float*)d_in[4];
    float* out = (float*)d_out;

    cudaFuncSetAttribute(resRNN_kernel, cudaFuncAttributeMaxDynamicSharedMemorySize, SMEM_BYTES);

    dim3 grid(8, 16, 1);   // cluster_dims (8,1,1): one cluster per rowgroup
    dim3 block(TPB, 1, 1);
    resRNN_kernel<<<grid, block, SMEM_BYTES>>>(x, W1, b1, W2, b2, out);
}